// round 1
// baseline (speedup 1.0000x reference)
#include <cuda_runtime.h>
#include <cuda_bf16.h>

// Problem constants
#define NPTS   16384          // SIZE = 128*128
#define BATCH  32
#define KNN    16
#define NDER   5              // order-2 2D: dx, dy, dx^2/2, dx*dy, dy^2/2

// One thread per (batch, point).
// Loads its 16 neighbor indices (int4 x4) and weights (float4 x4) contiguously,
// gathers neighbor coords/values (L2-resident, per-batch working set ~192KB),
// accumulates symmetric 5x5 normal equations in registers, solves with
// fully-unrolled Gaussian elimination (SPD + ridge -> no pivoting).
__global__ __launch_bounds__(256) void tp_layer_kernel(
    const float*  __restrict__ x,          // [B, NPTS]
    const float*  __restrict__ points,     // [B, NPTS, 2]
    const int*    __restrict__ edge_index, // [B, NPTS*KNN]
    const float*  __restrict__ dt_ptr,     // [1]
    const float*  __restrict__ dist,       // [B, NPTS, KNN]
    const float*  __restrict__ weight,     // [5]
    float*        __restrict__ out)        // [B, NPTS]
{
    const int gid = blockIdx.x * blockDim.x + threadIdx.x;
    if (gid >= BATCH * NPTS) return;
    const int b = gid >> 14;          // / NPTS
    const int s = gid & (NPTS - 1);

    const float* __restrict__ pb = points + (size_t)b * NPTS * 2;
    const float* __restrict__ xb = x + (size_t)b * NPTS;

    const float2 pc = *reinterpret_cast<const float2*>(pb + 2 * s);
    const float  v  = xb[s];

    const int4*   ei = reinterpret_cast<const int4*>(
        edge_index + (size_t)b * NPTS * KNN + (size_t)s * KNN);
    const float4* dw = reinterpret_cast<const float4*>(
        dist + (size_t)b * NPTS * KNN + (size_t)s * KNN);

    // Upper-triangular AtA (row-major packed) and Atb
    float ata[15];
    float atb[NDER];
    #pragma unroll
    for (int i = 0; i < 15; i++) ata[i] = 0.0f;
    #pragma unroll
    for (int i = 0; i < NDER; i++) atb[i] = 0.0f;

    #pragma unroll
    for (int c = 0; c < 4; c++) {
        const int4   e4 = ei[c];
        const float4 w4 = dw[c];
        const int   es[4] = { e4.x, e4.y, e4.z, e4.w };
        const float ws[4] = { w4.x, w4.y, w4.z, w4.w };
        #pragma unroll
        for (int k = 0; k < 4; k++) {
            const int   e = es[k];
            const float w = ws[k];
            const float2 np_ = *reinterpret_cast<const float2*>(pb + 2 * e);
            const float dx = np_.x - pc.x;
            const float dy = np_.y - pc.y;
            // Taylor monomials, weighted
            float a0 = dx * w;
            float a1 = dy * w;
            float a2 = 0.5f * dx * dx * w;
            float a3 = dx * dy * w;
            float a4 = 0.5f * dy * dy * w;
            const float r = (xb[e] - v) * w;

            // symmetric AtA upper triangle
            ata[0]  += a0 * a0;
            ata[1]  += a0 * a1;
            ata[2]  += a0 * a2;
            ata[3]  += a0 * a3;
            ata[4]  += a0 * a4;
            ata[5]  += a1 * a1;
            ata[6]  += a1 * a2;
            ata[7]  += a1 * a3;
            ata[8]  += a1 * a4;
            ata[9]  += a2 * a2;
            ata[10] += a2 * a3;
            ata[11] += a2 * a4;
            ata[12] += a3 * a3;
            ata[13] += a3 * a4;
            ata[14] += a4 * a4;

            atb[0] += a0 * r;
            atb[1] += a1 * r;
            atb[2] += a2 * r;
            atb[3] += a3 * r;
            atb[4] += a4 * r;
        }
    }

    // Build full 5x5 with ridge, augmented with atb
    float M[NDER][NDER];
    float bb[NDER];
    {
        int p = 0;
        #pragma unroll
        for (int i = 0; i < NDER; i++) {
            #pragma unroll
            for (int j = i; j < NDER; j++) {
                M[i][j] = ata[p];
                M[j][i] = ata[p];
                p++;
            }
            M[i][i] += 1e-6f;
            bb[i] = atb[i];
        }
    }

    // Gaussian elimination (no pivot: SPD + ridge)
    #pragma unroll
    for (int i = 0; i < NDER; i++) {
        const float inv = __frcp_rn(M[i][i]);
        #pragma unroll
        for (int j = i + 1; j < NDER; j++) {
            const float f = M[j][i] * inv;
            #pragma unroll
            for (int k = i + 1; k < NDER; k++) {
                M[j][k] -= f * M[i][k];
            }
            bb[j] -= f * bb[i];
        }
    }
    float d[NDER];
    #pragma unroll
    for (int i = NDER - 1; i >= 0; i--) {
        float sum = bb[i];
        #pragma unroll
        for (int k = i + 1; k < NDER; k++) {
            sum -= M[i][k] * d[k];
        }
        d[i] = sum * __frcp_rn(M[i][i]);
    }

    // du = dot(deriv, weight); out = x + dt * du
    const float dt = dt_ptr[0];
    float du = 0.0f;
    #pragma unroll
    for (int i = 0; i < NDER; i++) du += d[i] * weight[i];

    out[gid] = v + dt * du;
}

extern "C" void kernel_launch(void* const* d_in, const int* in_sizes, int n_in,
                              void* d_out, int out_size) {
    const float* x      = (const float*)d_in[0];
    const float* points = (const float*)d_in[1];
    const int*   edge   = (const int*)d_in[2];
    const float* dt     = (const float*)d_in[3];
    const float* dist   = (const float*)d_in[4];
    const float* weight = (const float*)d_in[5];
    float* out = (float*)d_out;

    const int total = BATCH * NPTS;
    const int threads = 256;
    const int blocks = (total + threads - 1) / threads;
    tp_layer_kernel<<<blocks, threads>>>(x, points, edge, dt, dist, weight, out);
}

// round 2
// speedup vs baseline: 2.0792x; 2.0792x over previous
#include <cuda_runtime.h>
#include <cuda_bf16.h>

// Problem constants
#define NPTS   16384          // SIZE = 128*128
#define BATCH  32
#define KNN    16
#define NDER   5              // order-2 2D: dx, dy, dx^2/2, dx*dy, dy^2/2

#define CTAS_PER_BATCH 4
#define THREADS 512
#define PTS_PER_CTA (NPTS / CTAS_PER_BATCH)     // 4096
#define ITERS (PTS_PER_CTA / THREADS)           // 8

// Dynamic smem: points[NPTS] float2 (128KB) + values[NPTS] float (64KB) = 192KB
#define SMEM_BYTES (NPTS * 2 * 4 + NPTS * 4)

__global__ __launch_bounds__(THREADS, 1) void tp_layer_kernel(
    const float*  __restrict__ x,          // [B, NPTS]
    const float*  __restrict__ points,     // [B, NPTS, 2]
    const int*    __restrict__ edge_index, // [B, NPTS*KNN]
    const float*  __restrict__ dt_ptr,     // [1]
    const float*  __restrict__ dist,       // [B, NPTS, KNN]
    const float*  __restrict__ weight,     // [5]
    float*        __restrict__ out)        // [B, NPTS]
{
    extern __shared__ float smem[];
    float2* __restrict__ sp = reinterpret_cast<float2*>(smem);   // [NPTS]
    float*  __restrict__ sv = smem + 2 * NPTS;                   // [NPTS]

    const int tid = threadIdx.x;
    const int b   = blockIdx.x / CTAS_PER_BATCH;
    const int c0  = (blockIdx.x % CTAS_PER_BATCH) * PTS_PER_CTA;

    const float* __restrict__ pb = points + (size_t)b * NPTS * 2;
    const float* __restrict__ xb = x + (size_t)b * NPTS;

    // Stage whole batch: points (8192 float4) + x (4096 float4), coalesced.
    {
        const float4* __restrict__ srcp = reinterpret_cast<const float4*>(pb);
        float4* dstp = reinterpret_cast<float4*>(smem);
        #pragma unroll
        for (int i = 0; i < (NPTS * 2 / 4) / THREADS; i++)
            dstp[tid + i * THREADS] = srcp[tid + i * THREADS];
        const float4* __restrict__ srcv = reinterpret_cast<const float4*>(xb);
        float4* dstv = reinterpret_cast<float4*>(sv);
        #pragma unroll
        for (int i = 0; i < (NPTS / 4) / THREADS; i++)
            dstv[tid + i * THREADS] = srcv[tid + i * THREADS];
    }
    __syncthreads();

    const float dt = dt_ptr[0];
    float wv[NDER];
    #pragma unroll
    for (int i = 0; i < NDER; i++) wv[i] = weight[i];

    for (int it = 0; it < ITERS; it++) {
        const int s = c0 + it * THREADS + tid;   // point index within batch

        const float2 pc = sp[s];
        const float  v  = sv[s];

        const int4*   ei = reinterpret_cast<const int4*>(
            edge_index + (size_t)b * NPTS * KNN + (size_t)s * KNN);
        const float4* dw = reinterpret_cast<const float4*>(
            dist + (size_t)b * NPTS * KNN + (size_t)s * KNN);

        float ata[15];
        float atb[NDER];
        #pragma unroll
        for (int i = 0; i < 15; i++) ata[i] = 0.0f;
        #pragma unroll
        for (int i = 0; i < NDER; i++) atb[i] = 0.0f;

        #pragma unroll
        for (int cc = 0; cc < 4; cc++) {
            const int4   e4 = ei[cc];
            const float4 w4 = dw[cc];
            const int   es[4] = { e4.x, e4.y, e4.z, e4.w };
            const float ws[4] = { w4.x, w4.y, w4.z, w4.w };
            #pragma unroll
            for (int k = 0; k < 4; k++) {
                const int   e = es[k];
                const float w = ws[k];
                const float2 np_ = sp[e];
                const float dx = np_.x - pc.x;
                const float dy = np_.y - pc.y;
                float a0 = dx * w;
                float a1 = dy * w;
                float a2 = 0.5f * dx * dx * w;
                float a3 = dx * dy * w;
                float a4 = 0.5f * dy * dy * w;
                const float r = (sv[e] - v) * w;

                ata[0]  += a0 * a0;
                ata[1]  += a0 * a1;
                ata[2]  += a0 * a2;
                ata[3]  += a0 * a3;
                ata[4]  += a0 * a4;
                ata[5]  += a1 * a1;
                ata[6]  += a1 * a2;
                ata[7]  += a1 * a3;
                ata[8]  += a1 * a4;
                ata[9]  += a2 * a2;
                ata[10] += a2 * a3;
                ata[11] += a2 * a4;
                ata[12] += a3 * a3;
                ata[13] += a3 * a4;
                ata[14] += a4 * a4;

                atb[0] += a0 * r;
                atb[1] += a1 * r;
                atb[2] += a2 * r;
                atb[3] += a3 * r;
                atb[4] += a4 * r;
            }
        }

        // Full 5x5 with ridge
        float M[NDER][NDER];
        float bb[NDER];
        {
            int p = 0;
            #pragma unroll
            for (int i = 0; i < NDER; i++) {
                #pragma unroll
                for (int j = i; j < NDER; j++) {
                    M[i][j] = ata[p];
                    M[j][i] = ata[p];
                    p++;
                }
                M[i][i] += 1e-6f;
                bb[i] = atb[i];
            }
        }

        // Gaussian elimination, no pivoting (SPD + ridge)
        #pragma unroll
        for (int i = 0; i < NDER; i++) {
            const float inv = __frcp_rn(M[i][i]);
            #pragma unroll
            for (int j = i + 1; j < NDER; j++) {
                const float f = M[j][i] * inv;
                #pragma unroll
                for (int k = i + 1; k < NDER; k++) {
                    M[j][k] -= f * M[i][k];
                }
                bb[j] -= f * bb[i];
            }
        }
        float d[NDER];
        #pragma unroll
        for (int i = NDER - 1; i >= 0; i--) {
            float sum = bb[i];
            #pragma unroll
            for (int k = i + 1; k < NDER; k++) {
                sum -= M[i][k] * d[k];
            }
            d[i] = sum * __frcp_rn(M[i][i]);
        }

        float du = 0.0f;
        #pragma unroll
        for (int i = 0; i < NDER; i++) du += d[i] * wv[i];

        out[(size_t)b * NPTS + s] = v + dt * du;
    }
}

extern "C" void kernel_launch(void* const* d_in, const int* in_sizes, int n_in,
                              void* d_out, int out_size) {
    const float* x      = (const float*)d_in[0];
    const float* points = (const float*)d_in[1];
    const int*   edge   = (const int*)d_in[2];
    const float* dt     = (const float*)d_in[3];
    const float* dist   = (const float*)d_in[4];
    const float* weight = (const float*)d_in[5];
    float* out = (float*)d_out;

    cudaFuncSetAttribute(tp_layer_kernel,
                         cudaFuncAttributeMaxDynamicSharedMemorySize, SMEM_BYTES);

    tp_layer_kernel<<<BATCH * CTAS_PER_BATCH, THREADS, SMEM_BYTES>>>(
        x, points, edge, dt, dist, weight, out);
}